// round 1
// baseline (speedup 1.0000x reference)
#include <cuda_runtime.h>

// Problem constants
#define Bn 4
#define Tn 4096
#define En 1024
#define Hn 64
#define SCALE 0.03125f   // 1024^-0.5 exactly

typedef unsigned long long u64;

// Scratch for projected q/k/v: [B, T, H] fp32 each (4 MB each)
__device__ float g_q[Bn * Tn * Hn];
__device__ float g_k[Bn * Tn * Hn];
__device__ float g_v[Bn * Tn * Hn];

// ---------------- packed f32x2 helpers (sm_100+ PTX) ----------------
__device__ __forceinline__ u64 ld2(const float* p) {
    return *reinterpret_cast<const u64*>(p);   // LDS.64 / LDG.64 of contiguous pair
}
__device__ __forceinline__ void fma2(u64& acc, u64 a, u64 b) {
    asm("fma.rn.f32x2 %0, %1, %2, %0;" : "+l"(acc) : "l"(a), "l"(b));
}
__device__ __forceinline__ void mul2(u64& acc, u64 b) {
    asm("mul.rn.f32x2 %0, %0, %1;" : "+l"(acc) : "l"(b));
}
__device__ __forceinline__ u64 dup2(float x) {
    u64 r; unsigned xi = __float_as_uint(x);
    asm("mov.b64 %0, {%1, %1};" : "=l"(r) : "r"(xi));
    return r;
}
__device__ __forceinline__ float lo2(u64 a) { return __uint_as_float((unsigned)a); }
__device__ __forceinline__ float hi2(u64 a) { return __uint_as_float((unsigned)(a >> 32)); }

// ---------------- QKV projection ----------------
// x[16384,1024] @ {Wq,Wk,Wv}[1024,64] -> g_q/g_k/g_v
// Block: 256 thr, 32 rows, K chunks of 32. Thread (tx=col 0..63, ty=rowgrp 0..3)
// computes 8 rows x 3 matrices, FFMA2 packed along k.
#define PBM 32
#define PKC 32
#define PST (PKC + 2)   // even stride -> 8B-aligned pairs

__global__ void __launch_bounds__(256, 1) qkv_kernel(
    const float* __restrict__ x,  const float* __restrict__ Wq,
    const float* __restrict__ Wk, const float* __restrict__ Wv)
{
    __shared__ float xs[PBM][PST];
    __shared__ float wst[192][PST];   // W chunk transposed: wst[c + 64*m][k]

    int tid = threadIdx.x;
    int tx = tid & 63;     // output column within 64
    int ty = tid >> 6;     // row group 0..3
    int row0 = blockIdx.x * PBM;

    u64 acc[8][3];
#pragma unroll
    for (int r = 0; r < 8; r++) { acc[r][0] = 0; acc[r][1] = 0; acc[r][2] = 0; }

    for (int k0 = 0; k0 < En; k0 += PKC) {
        // load x tile: 32x32 floats, one float4 per thread (coalesced)
        {
            int r = tid >> 3;
            int c = (tid & 7) * 4;
            float4 v = *reinterpret_cast<const float4*>(&x[(row0 + r) * En + k0 + c]);
            xs[r][c] = v.x; xs[r][c + 1] = v.y; xs[r][c + 2] = v.z; xs[r][c + 3] = v.w;
        }
        // load W chunks transposed (k becomes the contiguous axis)
        {
            const float* Ws[3] = { Wq, Wk, Wv };
#pragma unroll
            for (int m = 0; m < 3; m++) {
#pragma unroll
                for (int it = 0; it < 2; it++) {
                    int idx = tid + it * 256;        // 512 float4 = 32k x 64c
                    int kk = idx >> 4;
                    int c = (idx & 15) * 4;
                    float4 v = *reinterpret_cast<const float4*>(&Ws[m][(k0 + kk) * Hn + c]);
                    wst[c + 0 + 64 * m][kk] = v.x;
                    wst[c + 1 + 64 * m][kk] = v.y;
                    wst[c + 2 + 64 * m][kk] = v.z;
                    wst[c + 3 + 64 * m][kk] = v.w;
                }
            }
        }
        __syncthreads();

#pragma unroll
        for (int k = 0; k < PKC; k += 2) {
            u64 w0 = ld2(&wst[tx][k]);
            u64 w1 = ld2(&wst[tx + 64][k]);
            u64 w2 = ld2(&wst[tx + 128][k]);
#pragma unroll
            for (int r = 0; r < 8; r++) {
                u64 xv = ld2(&xs[ty + 4 * r][k]);   // broadcast within warp
                fma2(acc[r][0], xv, w0);
                fma2(acc[r][1], xv, w1);
                fma2(acc[r][2], xv, w2);
            }
        }
        __syncthreads();
    }

#pragma unroll
    for (int r = 0; r < 8; r++) {
        int row = row0 + ty + 4 * r;
        g_q[row * Hn + tx] = lo2(acc[r][0]) + hi2(acc[r][0]);
        g_k[row * Hn + tx] = lo2(acc[r][1]) + hi2(acc[r][1]);
        g_v[row * Hn + tx] = lo2(acc[r][2]) + hi2(acc[r][2]);
    }
}

// ---------------- Flash attention (fp32, online softmax) ----------------
// Block: 256 thr = 16(ti: row groups) x 16(tj). Q tile 64 rows, key tiles of 64.
// Thread owns S rows i = ti+16*ii (ii<4), S cols j = tj+16*jj (jj<4),
// O cols h = 4*tj + {0..3}. Row stats reduced over the 16 tj lanes via shfl.
// Load balance: block handles qt = 63-pr then qt = pr  -> 65 key tiles each.
#define AST 66      // smem row stride (even => 8B-aligned k-pairs)
#define NQT 64      // T / 64

__global__ void __launch_bounds__(256, 1) attn_kernel(float* __restrict__ out)
{
    extern __shared__ float sm[];
    float* qs = sm;
    float* ks = sm + 64 * AST;
    float* vs = sm + 2 * 64 * AST;
    float* ps = sm + 3 * 64 * AST;

    int tid = threadIdx.x;
    int ti = tid >> 4;
    int tj = tid & 15;
    int b  = blockIdx.x & 3;
    int pr = blockIdx.x >> 2;   // 0..31

    const float* kg = g_k + (size_t)b * Tn * Hn;
    const float* vg = g_v + (size_t)b * Tn * Hn;

    for (int hf = 0; hf < 2; hf++) {
        int qt = hf ? pr : (NQT - 1 - pr);
        const float* qg = g_q + ((size_t)b * Tn + qt * 64) * Hn;

        __syncthreads();   // protect smem from previous half's readers
#pragma unroll
        for (int it = 0; it < 4; it++) {
            int idx = tid + it * 256;
            int r = idx >> 4;
            int c = (idx & 15) * 4;
            float4 v = *reinterpret_cast<const float4*>(&qg[r * Hn + c]);
            qs[r * AST + c] = v.x; qs[r * AST + c + 1] = v.y;
            qs[r * AST + c + 2] = v.z; qs[r * AST + c + 3] = v.w;
        }

        u64 o2[4][2];
        float m_i[4], l_i[4];
#pragma unroll
        for (int ii = 0; ii < 4; ii++) {
            o2[ii][0] = 0; o2[ii][1] = 0; m_i[ii] = -1e30f; l_i[ii] = 0.f;
        }

        for (int kt = 0; kt <= qt; kt++) {
            __syncthreads();   // prior stage-2 done with vs/ps before overwrite
            const float* kgt = kg + (size_t)kt * 64 * Hn;
            const float* vgt = vg + (size_t)kt * 64 * Hn;
#pragma unroll
            for (int it = 0; it < 4; it++) {
                int idx = tid + it * 256;
                int r = idx >> 4;
                int c = (idx & 15) * 4;
                float4 kv = *reinterpret_cast<const float4*>(&kgt[r * Hn + c]);
                ks[r * AST + c] = kv.x; ks[r * AST + c + 1] = kv.y;
                ks[r * AST + c + 2] = kv.z; ks[r * AST + c + 3] = kv.w;
                float4 vv = *reinterpret_cast<const float4*>(&vgt[r * Hn + c]);
                vs[r * AST + c] = vv.x; vs[r * AST + c + 1] = vv.y;
                vs[r * AST + c + 2] = vv.z; vs[r * AST + c + 3] = vv.w;
            }
            __syncthreads();

            // ---- stage 1: S = Q K^T (FFMA2 packed along k) ----
            u64 s2[4][4];
#pragma unroll
            for (int ii = 0; ii < 4; ii++)
#pragma unroll
                for (int jj = 0; jj < 4; jj++) s2[ii][jj] = 0;
#pragma unroll
            for (int k = 0; k < Hn; k += 2) {
                u64 qv[4], kv[4];
#pragma unroll
                for (int ii = 0; ii < 4; ii++) qv[ii] = ld2(&qs[(ti + 16 * ii) * AST + k]);
#pragma unroll
                for (int jj = 0; jj < 4; jj++) kv[jj] = ld2(&ks[(tj + 16 * jj) * AST + k]);
#pragma unroll
                for (int ii = 0; ii < 4; ii++)
#pragma unroll
                    for (int jj = 0; jj < 4; jj++)
                        fma2(s2[ii][jj], qv[ii], kv[jj]);
            }

            float s[4][4];
#pragma unroll
            for (int ii = 0; ii < 4; ii++)
#pragma unroll
                for (int jj = 0; jj < 4; jj++)
                    s[ii][jj] = (lo2(s2[ii][jj]) + hi2(s2[ii][jj])) * SCALE;

            if (kt == qt) {   // causal mask on the diagonal tile (local indices)
#pragma unroll
                for (int ii = 0; ii < 4; ii++)
#pragma unroll
                    for (int jj = 0; jj < 4; jj++)
                        if (tj + 16 * jj > ti + 16 * ii) s[ii][jj] = -1e30f;
            }

            // ---- online softmax ----
#pragma unroll
            for (int ii = 0; ii < 4; ii++) {
                float rm = fmaxf(fmaxf(s[ii][0], s[ii][1]), fmaxf(s[ii][2], s[ii][3]));
#pragma unroll
                for (int off = 8; off >= 1; off >>= 1)
                    rm = fmaxf(rm, __shfl_xor_sync(0xffffffffu, rm, off));
                float mn = fmaxf(m_i[ii], rm);
                float cs = __expf(m_i[ii] - mn);
                m_i[ii] = mn;
                float rs = 0.f;
#pragma unroll
                for (int jj = 0; jj < 4; jj++) {
                    float p = __expf(s[ii][jj] - mn);
                    s[ii][jj] = p;
                    rs += p;
                }
#pragma unroll
                for (int off = 8; off >= 1; off >>= 1)
                    rs += __shfl_xor_sync(0xffffffffu, rs, off);
                l_i[ii] = l_i[ii] * cs + rs;
                u64 c2 = dup2(cs);
                mul2(o2[ii][0], c2);
                mul2(o2[ii][1], c2);
#pragma unroll
                for (int jj = 0; jj < 4; jj++)
                    ps[(ti + 16 * ii) * AST + tj + 16 * jj] = s[ii][jj];
            }
            __syncthreads();

            // ---- stage 2: O += P V (FFMA2 packed along h) ----
#pragma unroll 4
            for (int j = 0; j < 64; j++) {
                u64 v0 = ld2(&vs[j * AST + 4 * tj]);
                u64 v1 = ld2(&vs[j * AST + 4 * tj + 2]);
#pragma unroll
                for (int ii = 0; ii < 4; ii++) {
                    u64 p2 = dup2(ps[(ti + 16 * ii) * AST + j]);
                    fma2(o2[ii][0], p2, v0);
                    fma2(o2[ii][1], p2, v1);
                }
            }
        }

        // ---- epilogue ----
#pragma unroll
        for (int ii = 0; ii < 4; ii++) {
            float inv = 1.f / l_i[ii];
            float4 r;
            r.x = lo2(o2[ii][0]) * inv;
            r.y = hi2(o2[ii][0]) * inv;
            r.z = lo2(o2[ii][1]) * inv;
            r.w = hi2(o2[ii][1]) * inv;
            *reinterpret_cast<float4*>(
                &out[((size_t)b * Tn + qt * 64 + ti + 16 * ii) * Hn + 4 * tj]) = r;
        }
    }
}

// ---------------- launcher ----------------
extern "C" void kernel_launch(void* const* d_in, const int* in_sizes, int n_in,
                              void* d_out, int out_size)
{
    const float* x  = (const float*)d_in[0];
    const float* Wq = (const float*)d_in[1];
    const float* Wk = (const float*)d_in[2];
    const float* Wv = (const float*)d_in[3];
    float* out = (float*)d_out;

    qkv_kernel<<<(Bn * Tn) / PBM, 256>>>(x, Wq, Wk, Wv);

    int smem = 4 * 64 * AST * (int)sizeof(float);   // 67584 B
    cudaFuncSetAttribute(attn_kernel, cudaFuncAttributeMaxDynamicSharedMemorySize, smem);
    attn_kernel<<<Bn * 32, 256, smem>>>(out);
}

// round 2
// speedup vs baseline: 2.1414x; 2.1414x over previous
#include <cuda_runtime.h>

#define Bn 4
#define Tn 4096
#define En 1024
#define Hn 64
#define SCALE 0.03125f   // 1024^-0.5

typedef unsigned uu;

// Projected q/k/v scratch: [B,T,H] fp32
__device__ float g_q[Bn * Tn * Hn];
__device__ float g_k[Bn * Tn * Hn];
__device__ float g_v[Bn * Tn * Hn];

__device__ __forceinline__ uu f2tf(float f) {
    uu r; asm("cvt.rna.tf32.f32 %0, %1;" : "=r"(r) : "f"(f)); return r;
}

// D += A(16x8,row) * B(8x8,col), tf32 in, fp32 accum
__device__ __forceinline__ void mma8(float c[4], const uu a[4], const uu b[2]) {
    asm("mma.sync.aligned.m16n8k8.row.col.f32.tf32.tf32.f32 "
        "{%0,%1,%2,%3}, {%4,%5,%6,%7}, {%8,%9}, {%0,%1,%2,%3};"
        : "+f"(c[0]), "+f"(c[1]), "+f"(c[2]), "+f"(c[3])
        : "r"(a[0]), "r"(a[1]), "r"(a[2]), "r"(a[3]), "r"(b[0]), "r"(b[1]));
}

// ================= QKV projection: x[16384,1024] @ W[1024,64] x3 =================
// Block: 128 thr (4 warps). Block tile: 64 rows x 192 cols, K chunks of 64.
// Warp w owns cols [48w, 48w+48) (6 n-tiles), all 64 rows (4 row-blocks).
#define XS_ST 68    // 68 mod 32 == 4 -> fragment banks = 4*gr + t (conflict-free)
#define WS_ST 196   // 196 mod 32 == 4

__global__ void __launch_bounds__(128, 1) qkv_kernel(
    const float* __restrict__ x,  const float* __restrict__ Wq,
    const float* __restrict__ Wk, const float* __restrict__ Wv)
{
    extern __shared__ uu sm[];
    uu* xs = sm;                 // [64][XS_ST]  x tile (tf32)
    uu* ws = sm + 64 * XS_ST;    // [64][WS_ST]  W chunk (tf32), n = 0..191

    const int tid = threadIdx.x;
    const int w = tid >> 5, lane = tid & 31, gr = lane >> 2, t = lane & 3;
    const int row0 = blockIdx.x * 64;
    const float* Ws[3] = { Wq, Wk, Wv };

    float acc[4][6][4];   // [row-block][n-tile][c-frag]
#pragma unroll
    for (int rb = 0; rb < 4; rb++)
#pragma unroll
        for (int nt = 0; nt < 6; nt++)
#pragma unroll
            for (int c = 0; c < 4; c++) acc[rb][nt][c] = 0.f;

    for (int k0 = 0; k0 < En; k0 += 64) {
        __syncthreads();
        // x tile: 64 rows x 64 k  (1024 float4)
#pragma unroll
        for (int it = 0; it < 8; it++) {
            int idx = tid + it * 128;
            int r = idx >> 4, c = (idx & 15) * 4;
            float4 v = *(const float4*)&x[(size_t)(row0 + r) * En + k0 + c];
            uint4 u = make_uint4(f2tf(v.x), f2tf(v.y), f2tf(v.z), f2tf(v.w));
            *(uint4*)&xs[r * XS_ST + c] = u;
        }
        // W chunk: 64 k x 192 n  (3072 float4)
#pragma unroll
        for (int it = 0; it < 24; it++) {
            int idx = tid + it * 128;
            int kk = idx / 48, rem = idx % 48, n4 = rem * 4;
            int m = n4 >> 6, col = n4 & 63;
            float4 v = *(const float4*)&Ws[m][(size_t)(k0 + kk) * Hn + col];
            uint4 u = make_uint4(f2tf(v.x), f2tf(v.y), f2tf(v.z), f2tf(v.w));
            *(uint4*)&ws[kk * WS_ST + n4] = u;
        }
        __syncthreads();

#pragma unroll
        for (int kk = 0; kk < 8; kk++) {
            uu a[4][4];
#pragma unroll
            for (int rb = 0; rb < 4; rb++) {
                int r = rb * 16 + gr;
                a[rb][0] = xs[r * XS_ST + kk * 8 + t];
                a[rb][1] = xs[(r + 8) * XS_ST + kk * 8 + t];
                a[rb][2] = xs[r * XS_ST + kk * 8 + t + 4];
                a[rb][3] = xs[(r + 8) * XS_ST + kk * 8 + t + 4];
            }
#pragma unroll
            for (int nt = 0; nt < 6; nt++) {
                int n0 = w * 48 + nt * 8;
                uu b[2];
                b[0] = ws[(kk * 8 + t) * WS_ST + n0 + gr];
                b[1] = ws[(kk * 8 + t + 4) * WS_ST + n0 + gr];
#pragma unroll
                for (int rb = 0; rb < 4; rb++) mma8(acc[rb][nt], a[rb], b);
            }
        }
    }

    // epilogue: scatter to g_q/g_k/g_v (n-tiles never straddle matrix bounds)
#pragma unroll
    for (int nt = 0; nt < 6; nt++) {
        int n = w * 48 + nt * 8 + 2 * t;
        float* base = (n < 64) ? g_q : (n < 128 ? g_k : g_v);
        int nc = n & 63;
#pragma unroll
        for (int rb = 0; rb < 4; rb++) {
            int r = row0 + rb * 16 + gr;
            *(float2*)&base[(size_t)r * Hn + nc] =
                make_float2(acc[rb][nt][0], acc[rb][nt][1]);
            *(float2*)&base[(size_t)(r + 8) * Hn + nc] =
                make_float2(acc[rb][nt][2], acc[rb][nt][3]);
        }
    }
}

// ================= Flash attention, tf32 mma, fp32 online softmax =================
// Block: 128 thr (4 warps). Q tile 64 rows (warp w: rows 16w..16w+15), K/V tiles 64.
// Load balance: block = (b, pr); processes qt = 63-pr then qt = pr (65 kt-tiles).
#define AS 68

__global__ void __launch_bounds__(128, 1) attn_kernel(float* __restrict__ out)
{
    extern __shared__ uu sm[];
    uu* ks = sm;                 // [64][AS] K tile (tf32), row = key idx, col = h
    uu* vs = sm + 64 * AS;       // [64][AS] V tile (tf32), row = key idx, col = h
    uu* ps = sm + 2 * 64 * AS;   // [64][AS] P (tf32), warp w owns rows 16w..16w+15

    const int tid = threadIdx.x;
    const int w = tid >> 5, lane = tid & 31, gr = lane >> 2, t = lane & 3;
    const int b = blockIdx.x & 3, pr = blockIdx.x >> 2;
    const float* kg = g_k + (size_t)b * Tn * Hn;
    const float* vg = g_v + (size_t)b * Tn * Hn;

    for (int hf = 0; hf < 2; hf++) {
        const int qt = hf ? pr : 63 - pr;

        // Q fragments, persistent in registers, SCALE folded in
        const float* qg = g_q + ((size_t)b * Tn + qt * 64 + w * 16) * Hn;
        uu qa[8][4];
#pragma unroll
        for (int kk = 0; kk < 8; kk++) {
            qa[kk][0] = f2tf(qg[(size_t)gr * Hn + kk * 8 + t] * SCALE);
            qa[kk][1] = f2tf(qg[(size_t)(gr + 8) * Hn + kk * 8 + t] * SCALE);
            qa[kk][2] = f2tf(qg[(size_t)gr * Hn + kk * 8 + t + 4] * SCALE);
            qa[kk][3] = f2tf(qg[(size_t)(gr + 8) * Hn + kk * 8 + t + 4] * SCALE);
        }

        float o[8][4];
        float m0 = -1e30f, m1 = -1e30f, l0 = 0.f, l1 = 0.f;
#pragma unroll
        for (int nt = 0; nt < 8; nt++)
#pragma unroll
            for (int c = 0; c < 4; c++) o[nt][c] = 0.f;

        for (int kt = 0; kt <= qt; kt++) {
            __syncthreads();   // previous iteration's vs/ps consumers done
            const float* kp = kg + (size_t)kt * 64 * Hn;
            const float* vp = vg + (size_t)kt * 64 * Hn;
#pragma unroll
            for (int it = 0; it < 8; it++) {
                int idx = tid + it * 128;
                int r = idx >> 4, c = (idx & 15) * 4;
                float4 kv = *(const float4*)&kp[(size_t)r * Hn + c];
                *(uint4*)&ks[r * AS + c] =
                    make_uint4(f2tf(kv.x), f2tf(kv.y), f2tf(kv.z), f2tf(kv.w));
                float4 vv = *(const float4*)&vp[(size_t)r * Hn + c];
                *(uint4*)&vs[r * AS + c] =
                    make_uint4(f2tf(vv.x), f2tf(vv.y), f2tf(vv.z), f2tf(vv.w));
            }
            __syncthreads();

            // ---- stage 1: S = (Q*scale) K^T ----
            float s[8][4];
#pragma unroll
            for (int nt = 0; nt < 8; nt++)
#pragma unroll
                for (int c = 0; c < 4; c++) s[nt][c] = 0.f;
#pragma unroll
            for (int kk = 0; kk < 8; kk++) {
#pragma unroll
                for (int nt = 0; nt < 8; nt++) {
                    uu bf[2];
                    bf[0] = ks[(nt * 8 + gr) * AS + kk * 8 + t];
                    bf[1] = ks[(nt * 8 + gr) * AS + kk * 8 + t + 4];
                    mma8(s[nt], qa[kk], bf);
                }
            }

            if (kt == qt) {   // causal mask, local indices within 64x64 diag tile
                int r0 = w * 16 + gr, r1 = r0 + 8;
#pragma unroll
                for (int nt = 0; nt < 8; nt++) {
                    int c0 = nt * 8 + 2 * t;
                    if (c0 > r0)     s[nt][0] = -1e30f;
                    if (c0 + 1 > r0) s[nt][1] = -1e30f;
                    if (c0 > r1)     s[nt][2] = -1e30f;
                    if (c0 + 1 > r1) s[nt][3] = -1e30f;
                }
            }

            // ---- online softmax (rows gr / gr+8; stats shared by 4 lanes) ----
            float rm0 = -1e30f, rm1 = -1e30f;
#pragma unroll
            for (int nt = 0; nt < 8; nt++) {
                rm0 = fmaxf(rm0, fmaxf(s[nt][0], s[nt][1]));
                rm1 = fmaxf(rm1, fmaxf(s[nt][2], s[nt][3]));
            }
            rm0 = fmaxf(rm0, __shfl_xor_sync(~0u, rm0, 1));
            rm0 = fmaxf(rm0, __shfl_xor_sync(~0u, rm0, 2));
            rm1 = fmaxf(rm1, __shfl_xor_sync(~0u, rm1, 1));
            rm1 = fmaxf(rm1, __shfl_xor_sync(~0u, rm1, 2));
            float nm0 = fmaxf(m0, rm0), nm1 = fmaxf(m1, rm1);
            float cr0 = __expf(m0 - nm0), cr1 = __expf(m1 - nm1);
            m0 = nm0; m1 = nm1;

            float rs0 = 0.f, rs1 = 0.f;
            uu* pw = ps + (w * 16) * AS;
#pragma unroll
            for (int nt = 0; nt < 8; nt++) {
                float p0 = __expf(s[nt][0] - nm0), p1 = __expf(s[nt][1] - nm0);
                float p2 = __expf(s[nt][2] - nm1), p3 = __expf(s[nt][3] - nm1);
                rs0 += p0 + p1; rs1 += p2 + p3;
                o[nt][0] *= cr0; o[nt][1] *= cr0; o[nt][2] *= cr1; o[nt][3] *= cr1;
                *(uint2*)&pw[gr * AS + nt * 8 + 2 * t] = make_uint2(f2tf(p0), f2tf(p1));
                *(uint2*)&pw[(gr + 8) * AS + nt * 8 + 2 * t] = make_uint2(f2tf(p2), f2tf(p3));
            }
            rs0 += __shfl_xor_sync(~0u, rs0, 1);
            rs0 += __shfl_xor_sync(~0u, rs0, 2);
            rs1 += __shfl_xor_sync(~0u, rs1, 1);
            rs1 += __shfl_xor_sync(~0u, rs1, 2);
            l0 = l0 * cr0 + rs0;
            l1 = l1 * cr1 + rs1;
            __syncwarp();   // P strip is warp-private

            // ---- stage 2: O += P V ----
#pragma unroll
            for (int kk = 0; kk < 8; kk++) {
                uu pa[4];
                pa[0] = pw[gr * AS + kk * 8 + t];
                pa[1] = pw[(gr + 8) * AS + kk * 8 + t];
                pa[2] = pw[gr * AS + kk * 8 + t + 4];
                pa[3] = pw[(gr + 8) * AS + kk * 8 + t + 4];
#pragma unroll
                for (int nt = 0; nt < 8; nt++) {
                    uu vb[2];
                    vb[0] = vs[(kk * 8 + t) * AS + nt * 8 + gr];
                    vb[1] = vs[(kk * 8 + t + 4) * AS + nt * 8 + gr];
                    mma8(o[nt], pa, vb);
                }
            }
        }

        // ---- epilogue ----
        float inv0 = 1.f / l0, inv1 = 1.f / l1;
        int row = qt * 64 + w * 16 + gr;
        float* ob = out + ((size_t)b * Tn + row) * Hn;
#pragma unroll
        for (int nt = 0; nt < 8; nt++) {
            *(float2*)&ob[nt * 8 + 2 * t] =
                make_float2(o[nt][0] * inv0, o[nt][1] * inv0);
            *(float2*)&ob[(size_t)8 * Hn + nt * 8 + 2 * t] =
                make_float2(o[nt][2] * inv1, o[nt][3] * inv1);
        }
    }
}

// ================= launcher =================
extern "C" void kernel_launch(void* const* d_in, const int* in_sizes, int n_in,
                              void* d_out, int out_size)
{
    const float* x  = (const float*)d_in[0];
    const float* Wq = (const float*)d_in[1];
    const float* Wk = (const float*)d_in[2];
    const float* Wv = (const float*)d_in[3];
    float* out = (float*)d_out;

    int qkv_smem = (64 * XS_ST + 64 * WS_ST) * (int)sizeof(uu);   // 67584
    cudaFuncSetAttribute(qkv_kernel, cudaFuncAttributeMaxDynamicSharedMemorySize, qkv_smem);
    qkv_kernel<<<(Bn * Tn) / 64, 128, qkv_smem>>>(x, Wq, Wk, Wv);

    int attn_smem = 3 * 64 * AS * (int)sizeof(uu);                // 52224
    cudaFuncSetAttribute(attn_kernel, cudaFuncAttributeMaxDynamicSharedMemorySize, attn_smem);
    attn_kernel<<<Bn * 32, 128, attn_smem>>>(out);
}

// round 3
// speedup vs baseline: 2.3042x; 1.0760x over previous
#include <cuda_runtime.h>

#define Bn 4
#define Tn 4096
#define En 1024
#define Hn 64
#define SCALE 0.03125f   // 1024^-0.5

typedef unsigned uu;

// Projected q/k/v scratch: [B,T,H] fp32
__device__ float g_q[Bn * Tn * Hn];
__device__ float g_k[Bn * Tn * Hn];
__device__ float g_v[Bn * Tn * Hn];

__device__ __forceinline__ uu f2tf(float f) {
    uu r; asm("cvt.rna.tf32.f32 %0, %1;" : "=r"(r) : "f"(f)); return r;
}

// D += A(16x8,row) * B(8x8,col), tf32 in, fp32 accum
__device__ __forceinline__ void mma8(float c[4], const uu a[4], const uu b[2]) {
    asm("mma.sync.aligned.m16n8k8.row.col.f32.tf32.tf32.f32 "
        "{%0,%1,%2,%3}, {%4,%5,%6,%7}, {%8,%9}, {%0,%1,%2,%3};"
        : "+f"(c[0]), "+f"(c[1]), "+f"(c[2]), "+f"(c[3])
        : "r"(a[0]), "r"(a[1]), "r"(a[2]), "r"(a[3]), "r"(b[0]), "r"(b[1]));
}

// group-scoped named barrier (128 threads)
__device__ __forceinline__ void barg(int id) {
    asm volatile("bar.sync %0, %1;" :: "r"(id), "r"(128) : "memory");
}

// ================= QKV projection: x[16384,1024] @ W[1024,64] x3 =================
// Block: 128 thr (4 warps), 2 blocks/SM. Tile: 64 rows x 192 cols, K chunks of 32.
#define PKC 32
#define XS_ST 36    // mod 32 == 4 (conflict-free frags), mod 4 == 0 (uint4 align)
#define WS_ST 196

__global__ void __launch_bounds__(128, 2) qkv_kernel(
    const float* __restrict__ x,  const float* __restrict__ Wq,
    const float* __restrict__ Wk, const float* __restrict__ Wv)
{
    extern __shared__ uu sm[];
    uu* xs = sm;                 // [64][XS_ST]
    uu* ws = sm + 64 * XS_ST;    // [PKC][WS_ST], n = 0..191

    const int tid = threadIdx.x;
    const int w = tid >> 5, lane = tid & 31, gr = lane >> 2, t = lane & 3;
    const int row0 = blockIdx.x * 64;
    const float* Ws[3] = { Wq, Wk, Wv };

    float acc[4][6][4];
#pragma unroll
    for (int rb = 0; rb < 4; rb++)
#pragma unroll
        for (int nt = 0; nt < 6; nt++)
#pragma unroll
            for (int c = 0; c < 4; c++) acc[rb][nt][c] = 0.f;

    for (int k0 = 0; k0 < En; k0 += PKC) {
        __syncthreads();
        // x tile: 64 rows x 32 k (512 float4)
#pragma unroll
        for (int it = 0; it < 4; it++) {
            int idx = tid + it * 128;
            int r = idx >> 3, c = (idx & 7) * 4;
            float4 v = *(const float4*)&x[(size_t)(row0 + r) * En + k0 + c];
            *(uint4*)&xs[r * XS_ST + c] =
                make_uint4(f2tf(v.x), f2tf(v.y), f2tf(v.z), f2tf(v.w));
        }
        // W chunk: 32 k x 192 n (1536 float4)
#pragma unroll
        for (int it = 0; it < 12; it++) {
            int idx = tid + it * 128;
            int kk = idx / 48, n4 = (idx % 48) * 4;
            int m = n4 >> 6, col = n4 & 63;
            float4 v = *(const float4*)&Ws[m][(size_t)(k0 + kk) * Hn + col];
            *(uint4*)&ws[kk * WS_ST + n4] =
                make_uint4(f2tf(v.x), f2tf(v.y), f2tf(v.z), f2tf(v.w));
        }
        __syncthreads();

#pragma unroll
        for (int kk = 0; kk < PKC / 8; kk++) {
            uu a[4][4];
#pragma unroll
            for (int rb = 0; rb < 4; rb++) {
                int r = rb * 16 + gr;
                a[rb][0] = xs[r * XS_ST + kk * 8 + t];
                a[rb][1] = xs[(r + 8) * XS_ST + kk * 8 + t];
                a[rb][2] = xs[r * XS_ST + kk * 8 + t + 4];
                a[rb][3] = xs[(r + 8) * XS_ST + kk * 8 + t + 4];
            }
#pragma unroll
            for (int nt = 0; nt < 6; nt++) {
                int n0 = w * 48 + nt * 8;
                uu b[2];
                b[0] = ws[(kk * 8 + t) * WS_ST + n0 + gr];
                b[1] = ws[(kk * 8 + t + 4) * WS_ST + n0 + gr];
#pragma unroll
                for (int rb = 0; rb < 4; rb++) mma8(acc[rb][nt], a[rb], b);
            }
        }
    }

#pragma unroll
    for (int nt = 0; nt < 6; nt++) {
        int n = w * 48 + nt * 8 + 2 * t;
        float* base = (n < 64) ? g_q : (n < 128 ? g_k : g_v);
        int nc = n & 63;
#pragma unroll
        for (int rb = 0; rb < 4; rb++) {
            int r = row0 + rb * 16 + gr;
            *(float2*)&base[(size_t)r * Hn + nc] =
                make_float2(acc[rb][nt][0], acc[rb][nt][1]);
            *(float2*)&base[(size_t)(r + 8) * Hn + nc] =
                make_float2(acc[rb][nt][2], acc[rb][nt][3]);
        }
    }
}

// ================= Flash attention, split-K warp groups =================
// Block: 256 thr = 2 groups x 4 warps. Group g handles kt % 2 == g with private
// K/V/P buffers + named barriers. Online softmax per group; LSE-merge at end.
// Block (b, pr) does qt = 63-pr then qt = pr (65 key-tiles total, balanced).
#define AS 68

__global__ void __launch_bounds__(256, 1) attn_kernel(float* __restrict__ out)
{
    extern __shared__ uu sm[];
    const int tid = threadIdx.x;
    const int w = tid >> 5, lane = tid & 31, gr = lane >> 2, t = lane & 3;
    const int g = w >> 2, wq = w & 3;
    const int tg = tid & 127;

    uu* ksg = sm + (size_t)g * 64 * AS;             // ks0, ks1
    uu* vsg = sm + (size_t)(2 + g) * 64 * AS;       // vs0, vs1
    uu* psg = sm + (size_t)(4 + g) * 64 * AS;       // ps0, ps1
    float* M = (float*)(sm + (size_t)5 * 64 * AS);  // merge buffer (= ps1)

    const int b = blockIdx.x & 3, pr = blockIdx.x >> 2;
    const float* kg = g_k + (size_t)b * Tn * Hn;
    const float* vg = g_v + (size_t)b * Tn * Hn;

    for (int hf = 0; hf < 2; hf++) {
        const int qt = hf ? pr : 63 - pr;
        __syncthreads();   // all buffers free from previous half

        // Q fragments (scale folded), persistent in registers
        const float* qg = g_q + ((size_t)b * Tn + qt * 64 + wq * 16) * Hn;
        uu qa[8][4];
#pragma unroll
        for (int kk = 0; kk < 8; kk++) {
            qa[kk][0] = f2tf(qg[(size_t)gr * Hn + kk * 8 + t] * SCALE);
            qa[kk][1] = f2tf(qg[(size_t)(gr + 8) * Hn + kk * 8 + t] * SCALE);
            qa[kk][2] = f2tf(qg[(size_t)gr * Hn + kk * 8 + t + 4] * SCALE);
            qa[kk][3] = f2tf(qg[(size_t)(gr + 8) * Hn + kk * 8 + t + 4] * SCALE);
        }

        float o[8][4];
        float m0 = -1e30f, m1 = -1e30f, l0 = 0.f, l1 = 0.f;
#pragma unroll
        for (int nt = 0; nt < 8; nt++)
#pragma unroll
            for (int c = 0; c < 4; c++) o[nt][c] = 0.f;

        for (int kt = g; kt <= qt; kt += 2) {
            barg(g + 1);   // group's readers done with ksg/vsg
            const float* kp = kg + (size_t)kt * 64 * Hn;
            const float* vp = vg + (size_t)kt * 64 * Hn;
#pragma unroll
            for (int it = 0; it < 8; it++) {
                int idx = tg + it * 128;
                int r = idx >> 4, c = (idx & 15) * 4;
                float4 kv = *(const float4*)&kp[(size_t)r * Hn + c];
                *(uint4*)&ksg[r * AS + c] =
                    make_uint4(f2tf(kv.x), f2tf(kv.y), f2tf(kv.z), f2tf(kv.w));
                float4 vv = *(const float4*)&vp[(size_t)r * Hn + c];
                *(uint4*)&vsg[r * AS + c] =
                    make_uint4(f2tf(vv.x), f2tf(vv.y), f2tf(vv.z), f2tf(vv.w));
            }
            barg(g + 1);   // tile visible to group

            // ---- stage 1: S = (Q*scale) K^T ----
            float s[8][4];
#pragma unroll
            for (int nt = 0; nt < 8; nt++)
#pragma unroll
                for (int c = 0; c < 4; c++) s[nt][c] = 0.f;
#pragma unroll
            for (int kk = 0; kk < 8; kk++) {
#pragma unroll
                for (int nt = 0; nt < 8; nt++) {
                    uu bf[2];
                    bf[0] = ksg[(nt * 8 + gr) * AS + kk * 8 + t];
                    bf[1] = ksg[(nt * 8 + gr) * AS + kk * 8 + t + 4];
                    mma8(s[nt], qa[kk], bf);
                }
            }

            if (kt == qt) {   // causal mask on diagonal tile
                int r0 = wq * 16 + gr, r1 = r0 + 8;
#pragma unroll
                for (int nt = 0; nt < 8; nt++) {
                    int c0 = nt * 8 + 2 * t;
                    if (c0 > r0)     s[nt][0] = -1e30f;
                    if (c0 + 1 > r0) s[nt][1] = -1e30f;
                    if (c0 > r1)     s[nt][2] = -1e30f;
                    if (c0 + 1 > r1) s[nt][3] = -1e30f;
                }
            }

            // ---- online softmax ----
            float rm0 = -1e30f, rm1 = -1e30f;
#pragma unroll
            for (int nt = 0; nt < 8; nt++) {
                rm0 = fmaxf(rm0, fmaxf(s[nt][0], s[nt][1]));
                rm1 = fmaxf(rm1, fmaxf(s[nt][2], s[nt][3]));
            }
            rm0 = fmaxf(rm0, __shfl_xor_sync(~0u, rm0, 1));
            rm0 = fmaxf(rm0, __shfl_xor_sync(~0u, rm0, 2));
            rm1 = fmaxf(rm1, __shfl_xor_sync(~0u, rm1, 1));
            rm1 = fmaxf(rm1, __shfl_xor_sync(~0u, rm1, 2));
            float nm0 = fmaxf(m0, rm0), nm1 = fmaxf(m1, rm1);
            float cr0 = __expf(m0 - nm0), cr1 = __expf(m1 - nm1);
            m0 = nm0; m1 = nm1;

            float rs0 = 0.f, rs1 = 0.f;
            uu* pw = psg + (wq * 16) * AS;
#pragma unroll
            for (int nt = 0; nt < 8; nt++) {
                float p0 = __expf(s[nt][0] - nm0), p1 = __expf(s[nt][1] - nm0);
                float p2 = __expf(s[nt][2] - nm1), p3 = __expf(s[nt][3] - nm1);
                rs0 += p0 + p1; rs1 += p2 + p3;
                o[nt][0] *= cr0; o[nt][1] *= cr0; o[nt][2] *= cr1; o[nt][3] *= cr1;
                *(uint2*)&pw[gr * AS + nt * 8 + 2 * t] = make_uint2(f2tf(p0), f2tf(p1));
                *(uint2*)&pw[(gr + 8) * AS + nt * 8 + 2 * t] = make_uint2(f2tf(p2), f2tf(p3));
            }
            rs0 += __shfl_xor_sync(~0u, rs0, 1);
            rs0 += __shfl_xor_sync(~0u, rs0, 2);
            rs1 += __shfl_xor_sync(~0u, rs1, 1);
            rs1 += __shfl_xor_sync(~0u, rs1, 2);
            l0 = l0 * cr0 + rs0;
            l1 = l1 * cr1 + rs1;
            __syncwarp();   // P strip warp-private

            // ---- stage 2: O += P V ----
#pragma unroll
            for (int kk = 0; kk < 8; kk++) {
                uu pa[4];
                pa[0] = pw[gr * AS + kk * 8 + t];
                pa[1] = pw[(gr + 8) * AS + kk * 8 + t];
                pa[2] = pw[gr * AS + kk * 8 + t + 4];
                pa[3] = pw[(gr + 8) * AS + kk * 8 + t + 4];
#pragma unroll
                for (int nt = 0; nt < 8; nt++) {
                    uu vb[2];
                    vb[0] = vsg[(kk * 8 + t) * AS + nt * 8 + gr];
                    vb[1] = vsg[(kk * 8 + t + 4) * AS + nt * 8 + gr];
                    mma8(o[nt], pa, vb);
                }
            }
        }

        // ---- merge group partials (group 1 -> smem, group 0 combines) ----
        __syncwarp();   // lanes done reading P strip before overwrite
        if (g == 1) {
            int r0 = wq * 16 + gr, r1 = r0 + 8;
#pragma unroll
            for (int nt = 0; nt < 8; nt++) {
                *(float2*)&M[r0 * AS + nt * 8 + 2 * t] = make_float2(o[nt][0], o[nt][1]);
                *(float2*)&M[r1 * AS + nt * 8 + 2 * t] = make_float2(o[nt][2], o[nt][3]);
            }
            if (t == 0) {
                M[r0 * AS + 64] = m0; M[r0 * AS + 65] = l0;
                M[r1 * AS + 64] = m1; M[r1 * AS + 65] = l1;
            }
        }
        __syncthreads();
        if (g == 0) {
            int r0 = wq * 16 + gr, r1 = r0 + 8;
            float mo0 = M[r0 * AS + 64], lo0 = M[r0 * AS + 65];
            float mo1 = M[r1 * AS + 64], lo1 = M[r1 * AS + 65];
            float ms0 = fmaxf(m0, mo0), ms1 = fmaxf(m1, mo1);
            float f00 = __expf(m0 - ms0), f01 = __expf(mo0 - ms0);
            float f10 = __expf(m1 - ms1), f11 = __expf(mo1 - ms1);
            float inv0 = 1.f / (l0 * f00 + lo0 * f01);
            float inv1 = 1.f / (l1 * f10 + lo1 * f11);
            float* ob = out + ((size_t)b * Tn + qt * 64 + wq * 16 + gr) * Hn;
#pragma unroll
            for (int nt = 0; nt < 8; nt++) {
                float2 q0 = *(const float2*)&M[r0 * AS + nt * 8 + 2 * t];
                float2 q1 = *(const float2*)&M[r1 * AS + nt * 8 + 2 * t];
                *(float2*)&ob[nt * 8 + 2 * t] = make_float2(
                    (o[nt][0] * f00 + q0.x * f01) * inv0,
                    (o[nt][1] * f00 + q0.y * f01) * inv0);
                *(float2*)&ob[(size_t)8 * Hn + nt * 8 + 2 * t] = make_float2(
                    (o[nt][2] * f10 + q1.x * f11) * inv1,
                    (o[nt][3] * f10 + q1.y * f11) * inv1);
            }
        }
    }
}

// ================= launcher =================
extern "C" void kernel_launch(void* const* d_in, const int* in_sizes, int n_in,
                              void* d_out, int out_size)
{
    const float* x  = (const float*)d_in[0];
    const float* Wq = (const float*)d_in[1];
    const float* Wk = (const float*)d_in[2];
    const float* Wv = (const float*)d_in[3];
    float* out = (float*)d_out;

    int qkv_smem = (64 * XS_ST + PKC * WS_ST) * (int)sizeof(uu);   // 34304
    cudaFuncSetAttribute(qkv_kernel, cudaFuncAttributeMaxDynamicSharedMemorySize, qkv_smem);
    qkv_kernel<<<(Bn * Tn) / 64, 128, qkv_smem>>>(x, Wq, Wk, Wv);

    int attn_smem = 6 * 64 * AS * (int)sizeof(uu);                 // 104448
    cudaFuncSetAttribute(attn_kernel, cudaFuncAttributeMaxDynamicSharedMemorySize, attn_smem);
    attn_kernel<<<Bn * 32, 256, attn_smem>>>(out);
}

// round 4
// speedup vs baseline: 3.3753x; 1.4649x over previous
#include <cuda_runtime.h>

#define Bn 4
#define Tn 4096
#define En 1024
#define Hn 64
#define SCALE 0.03125f   // 1024^-0.5

typedef unsigned uu;

// Projected q/k/v scratch: [B,T,H] fp32
__device__ float g_q[Bn * Tn * Hn];
__device__ float g_k[Bn * Tn * Hn];
__device__ float g_v[Bn * Tn * Hn];

__device__ __forceinline__ uu f2tf(float f) {
    uu r; asm("cvt.rna.tf32.f32 %0, %1;" : "=r"(r) : "f"(f)); return r;
}

// D += A(16x8,row) * B(8x8,col), tf32 in, fp32 accum
__device__ __forceinline__ void mma8(float c[4], const uu a[4], const uu b[2]) {
    asm("mma.sync.aligned.m16n8k8.row.col.f32.tf32.tf32.f32 "
        "{%0,%1,%2,%3}, {%4,%5,%6,%7}, {%8,%9}, {%0,%1,%2,%3};"
        : "+f"(c[0]), "+f"(c[1]), "+f"(c[2]), "+f"(c[3])
        : "r"(a[0]), "r"(a[1]), "r"(a[2]), "r"(a[3]), "r"(b[0]), "r"(b[1]));
}

// group-scoped named barrier (128 threads)
__device__ __forceinline__ void barg(int id) {
    asm volatile("bar.sync %0, %1;" :: "r"(id), "r"(128) : "memory");
}

__device__ __forceinline__ void cpa16(void* s, const void* g) {
    unsigned sa = (unsigned)__cvta_generic_to_shared(s);
    asm volatile("cp.async.ca.shared.global [%0], [%1], 16;" :: "r"(sa), "l"(g));
}
__device__ __forceinline__ void cpa_commit() {
    asm volatile("cp.async.commit_group;" ::: "memory");
}
__device__ __forceinline__ void cpa_wait1() {
    asm volatile("cp.async.wait_group 1;" ::: "memory");
}

// ================= QKV projection: x[16384,1024] @ W[1024,64] x3 =================
// Block: 128 thr (4 warps), 2 blocks/SM. Tile: 64 rows x 192 cols, K chunks of 32.
// 2-stage cp.async pipeline, raw fp32 staging, tf32 cvt at fragment load.
#define PKC 32
#define XS_ST 36    // mod 32 == 4 (conflict-free frags), mod 4 == 0 (16B align)
#define WS_ST 196

__global__ void __launch_bounds__(128, 2) qkv_kernel(
    const float* __restrict__ x,  const float* __restrict__ Wq,
    const float* __restrict__ Wk, const float* __restrict__ Wv)
{
    extern __shared__ float smf[];
    // stages: xs[s] = smf + s*64*XS_ST ; ws[s] = smf + 2*64*XS_ST + s*PKC*WS_ST
    float* xsb = smf;
    float* wsb = smf + 2 * 64 * XS_ST;

    const int tid = threadIdx.x;
    const int w = tid >> 5, lane = tid & 31, gr = lane >> 2, t = lane & 3;
    const int row0 = blockIdx.x * 64;
    const float* Ws[3] = { Wq, Wk, Wv };

    float acc[4][6][4];
#pragma unroll
    for (int rb = 0; rb < 4; rb++)
#pragma unroll
        for (int nt = 0; nt < 6; nt++)
#pragma unroll
            for (int c = 0; c < 4; c++) acc[rb][nt][c] = 0.f;

    // issue helper (inlined twice): copies chunk k0 into stage s
    auto issue = [&](int k0, int s) {
        float* xs = xsb + s * 64 * XS_ST;
        float* ws = wsb + s * PKC * WS_ST;
#pragma unroll
        for (int it = 0; it < 4; it++) {
            int idx = tid + it * 128;
            int r = idx >> 3, c = (idx & 7) * 4;
            cpa16(&xs[r * XS_ST + c], &x[(size_t)(row0 + r) * En + k0 + c]);
        }
#pragma unroll
        for (int it = 0; it < 12; it++) {
            int idx = tid + it * 128;
            int kk = idx / 48, n4 = (idx % 48) * 4;
            int m = n4 >> 6, col = n4 & 63;
            cpa16(&ws[kk * WS_ST + n4], &Ws[m][(size_t)(k0 + kk) * Hn + col]);
        }
    };

    issue(0, 0);
    cpa_commit();

    for (int it = 0; it < En / PKC; it++) {
        __syncthreads();                    // previous compute done before overwrite
        if (it + 1 < En / PKC) issue((it + 1) * PKC, (it + 1) & 1);
        cpa_commit();
        cpa_wait1();                        // current stage resident
        __syncthreads();

        const float* xs = xsb + (it & 1) * 64 * XS_ST;
        const float* ws = wsb + (it & 1) * PKC * WS_ST;
#pragma unroll
        for (int kk = 0; kk < PKC / 8; kk++) {
            uu a[4][4];
#pragma unroll
            for (int rb = 0; rb < 4; rb++) {
                int r = rb * 16 + gr;
                a[rb][0] = f2tf(xs[r * XS_ST + kk * 8 + t]);
                a[rb][1] = f2tf(xs[(r + 8) * XS_ST + kk * 8 + t]);
                a[rb][2] = f2tf(xs[r * XS_ST + kk * 8 + t + 4]);
                a[rb][3] = f2tf(xs[(r + 8) * XS_ST + kk * 8 + t + 4]);
            }
#pragma unroll
            for (int nt = 0; nt < 6; nt++) {
                int n0 = w * 48 + nt * 8;
                uu b[2];
                b[0] = f2tf(ws[(kk * 8 + t) * WS_ST + n0 + gr]);
                b[1] = f2tf(ws[(kk * 8 + t + 4) * WS_ST + n0 + gr]);
#pragma unroll
                for (int rb = 0; rb < 4; rb++) mma8(acc[rb][nt], a[rb], b);
            }
        }
    }

#pragma unroll
    for (int nt = 0; nt < 6; nt++) {
        int n = w * 48 + nt * 8 + 2 * t;
        float* base = (n < 64) ? g_q : (n < 128 ? g_k : g_v);
        int nc = n & 63;
#pragma unroll
        for (int rb = 0; rb < 4; rb++) {
            int r = row0 + rb * 16 + gr;
            *(float2*)&base[(size_t)r * Hn + nc] =
                make_float2(acc[rb][nt][0], acc[rb][nt][1]);
            *(float2*)&base[(size_t)(r + 8) * Hn + nc] =
                make_float2(acc[rb][nt][2], acc[rb][nt][3]);
        }
    }
}

// ================= Flash attention, 3 split-K warp groups =================
// Block: 384 thr = 3 groups x 4 warps. Group g handles kt % 3 == g with private
// K/V/P buffers + named barriers. Shared Q tile in smem (loaded once per qt).
// Block (b, pr) does qt = 63-pr then qt = pr (65 key-tiles total, balanced).
#define AS 68
#define NG 3

__global__ void __launch_bounds__(384, 1) attn_kernel(float* __restrict__ out)
{
    extern __shared__ uu sm[];
    const int tid = threadIdx.x;
    const int w = tid >> 5, lane = tid & 31, gr = lane >> 2, t = lane & 3;
    const int g = w >> 2, wq = w & 3;
    const int tg = tid & 127;

    uu* qs  = sm;                                    // shared Q tile (scale folded)
    uu* ksg = sm + (size_t)(1 + g) * 64 * AS;
    uu* vsg = sm + (size_t)(4 + g) * 64 * AS;
    uu* psg = sm + (size_t)(7 + g) * 64 * AS;
    float* M1 = (float*)(sm + (size_t)8 * 64 * AS);  // group 1 partial (= its P)
    float* M2 = (float*)(sm + (size_t)9 * 64 * AS);  // group 2 partial (= its P)

    const int b = blockIdx.x & 3, pr = blockIdx.x >> 2;
    const float* kg = g_k + (size_t)b * Tn * Hn;
    const float* vg = g_v + (size_t)b * Tn * Hn;

    for (int hf = 0; hf < 2; hf++) {
        const int qt = hf ? pr : 63 - pr;
        __syncthreads();   // all buffers free from previous half

        // Q tile -> smem, tf32, SCALE folded (all 384 threads)
        const float* qg = g_q + ((size_t)b * Tn + qt * 64) * Hn;
        for (int idx = tid; idx < 1024; idx += 384) {
            int r = idx >> 4, c = (idx & 15) * 4;
            float4 v = *(const float4*)&qg[(size_t)r * Hn + c];
            *(uint4*)&qs[r * AS + c] = make_uint4(
                f2tf(v.x * SCALE), f2tf(v.y * SCALE),
                f2tf(v.z * SCALE), f2tf(v.w * SCALE));
        }
        __syncthreads();

        float o[8][4];
        float m0 = -1e30f, m1 = -1e30f, l0 = 0.f, l1 = 0.f;
#pragma unroll
        for (int nt = 0; nt < 8; nt++)
#pragma unroll
            for (int c = 0; c < 4; c++) o[nt][c] = 0.f;

        for (int kt = g; kt <= qt; kt += NG) {
            barg(g + 1);   // group's readers done with ksg/vsg
            const float* kp = kg + (size_t)kt * 64 * Hn;
            const float* vp = vg + (size_t)kt * 64 * Hn;
#pragma unroll
            for (int it = 0; it < 8; it++) {
                int idx = tg + it * 128;
                int r = idx >> 4, c = (idx & 15) * 4;
                float4 kv = *(const float4*)&kp[(size_t)r * Hn + c];
                *(uint4*)&ksg[r * AS + c] =
                    make_uint4(f2tf(kv.x), f2tf(kv.y), f2tf(kv.z), f2tf(kv.w));
                float4 vv = *(const float4*)&vp[(size_t)r * Hn + c];
                *(uint4*)&vsg[r * AS + c] =
                    make_uint4(f2tf(vv.x), f2tf(vv.y), f2tf(vv.z), f2tf(vv.w));
            }
            barg(g + 1);   // tile visible to group

            // ---- stage 1: S = (Q*scale) K^T ----
            float s[8][4];
#pragma unroll
            for (int nt = 0; nt < 8; nt++)
#pragma unroll
                for (int c = 0; c < 4; c++) s[nt][c] = 0.f;
#pragma unroll
            for (int kk = 0; kk < 8; kk++) {
                uu qa[4];
                int r0 = (wq * 16 + gr) * AS, r1 = (wq * 16 + gr + 8) * AS;
                qa[0] = qs[r0 + kk * 8 + t];
                qa[1] = qs[r1 + kk * 8 + t];
                qa[2] = qs[r0 + kk * 8 + t + 4];
                qa[3] = qs[r1 + kk * 8 + t + 4];
#pragma unroll
                for (int nt = 0; nt < 8; nt++) {
                    uu bf[2];
                    bf[0] = ksg[(nt * 8 + gr) * AS + kk * 8 + t];
                    bf[1] = ksg[(nt * 8 + gr) * AS + kk * 8 + t + 4];
                    mma8(s[nt], qa, bf);
                }
            }

            if (kt == qt) {   // causal mask on diagonal tile
                int r0 = wq * 16 + gr, r1 = r0 + 8;
#pragma unroll
                for (int nt = 0; nt < 8; nt++) {
                    int c0 = nt * 8 + 2 * t;
                    if (c0 > r0)     s[nt][0] = -1e30f;
                    if (c0 + 1 > r0) s[nt][1] = -1e30f;
                    if (c0 > r1)     s[nt][2] = -1e30f;
                    if (c0 + 1 > r1) s[nt][3] = -1e30f;
                }
            }

            // ---- online softmax ----
            float rm0 = -1e30f, rm1 = -1e30f;
#pragma unroll
            for (int nt = 0; nt < 8; nt++) {
                rm0 = fmaxf(rm0, fmaxf(s[nt][0], s[nt][1]));
                rm1 = fmaxf(rm1, fmaxf(s[nt][2], s[nt][3]));
            }
            rm0 = fmaxf(rm0, __shfl_xor_sync(~0u, rm0, 1));
            rm0 = fmaxf(rm0, __shfl_xor_sync(~0u, rm0, 2));
            rm1 = fmaxf(rm1, __shfl_xor_sync(~0u, rm1, 1));
            rm1 = fmaxf(rm1, __shfl_xor_sync(~0u, rm1, 2));
            float nm0 = fmaxf(m0, rm0), nm1 = fmaxf(m1, rm1);
            float cr0 = __expf(m0 - nm0), cr1 = __expf(m1 - nm1);
            m0 = nm0; m1 = nm1;

            float rs0 = 0.f, rs1 = 0.f;
            uu* pw = psg + (wq * 16) * AS;
#pragma unroll
            for (int nt = 0; nt < 8; nt++) {
                float p0 = __expf(s[nt][0] - nm0), p1 = __expf(s[nt][1] - nm0);
                float p2 = __expf(s[nt][2] - nm1), p3 = __expf(s[nt][3] - nm1);
                rs0 += p0 + p1; rs1 += p2 + p3;
                o[nt][0] *= cr0; o[nt][1] *= cr0; o[nt][2] *= cr1; o[nt][3] *= cr1;
                *(uint2*)&pw[gr * AS + nt * 8 + 2 * t] = make_uint2(f2tf(p0), f2tf(p1));
                *(uint2*)&pw[(gr + 8) * AS + nt * 8 + 2 * t] = make_uint2(f2tf(p2), f2tf(p3));
            }
            rs0 += __shfl_xor_sync(~0u, rs0, 1);
            rs0 += __shfl_xor_sync(~0u, rs0, 2);
            rs1 += __shfl_xor_sync(~0u, rs1, 1);
            rs1 += __shfl_xor_sync(~0u, rs1, 2);
            l0 = l0 * cr0 + rs0;
            l1 = l1 * cr1 + rs1;
            __syncwarp();   // P strip warp-private

            // ---- stage 2: O += P V ----
#pragma unroll
            for (int kk = 0; kk < 8; kk++) {
                uu pa[4];
                pa[0] = pw[gr * AS + kk * 8 + t];
                pa[1] = pw[(gr + 8) * AS + kk * 8 + t];
                pa[2] = pw[gr * AS + kk * 8 + t + 4];
                pa[3] = pw[(gr + 8) * AS + kk * 8 + t + 4];
#pragma unroll
                for (int nt = 0; nt < 8; nt++) {
                    uu vb[2];
                    vb[0] = vsg[(kk * 8 + t) * AS + nt * 8 + gr];
                    vb[1] = vsg[(kk * 8 + t + 4) * AS + nt * 8 + gr];
                    mma8(o[nt], pa, vb);
                }
            }
        }

        // ---- merge: groups 1,2 dump partials; group 0 combines ----
        __syncwarp();   // lanes done reading P strip before overwrite
        if (g > 0) {
            float* Mg = (g == 1) ? M1 : M2;
            int r0 = wq * 16 + gr, r1 = r0 + 8;
#pragma unroll
            for (int nt = 0; nt < 8; nt++) {
                *(float2*)&Mg[r0 * AS + nt * 8 + 2 * t] = make_float2(o[nt][0], o[nt][1]);
                *(float2*)&Mg[r1 * AS + nt * 8 + 2 * t] = make_float2(o[nt][2], o[nt][3]);
            }
            if (t == 0) {
                Mg[r0 * AS + 64] = m0; Mg[r0 * AS + 65] = l0;
                Mg[r1 * AS + 64] = m1; Mg[r1 * AS + 65] = l1;
            }
        }
        __syncthreads();
        if (g == 0) {
            int r0 = wq * 16 + gr, r1 = r0 + 8;
            float ma0 = M1[r0 * AS + 64], la0 = M1[r0 * AS + 65];
            float ma1 = M1[r1 * AS + 64], la1 = M1[r1 * AS + 65];
            float mb0 = M2[r0 * AS + 64], lb0 = M2[r0 * AS + 65];
            float mb1 = M2[r1 * AS + 64], lb1 = M2[r1 * AS + 65];
            float ms0 = fmaxf(fmaxf(m0, ma0), mb0);
            float ms1 = fmaxf(fmaxf(m1, ma1), mb1);
            float f00 = __expf(m0 - ms0), fa0 = __expf(ma0 - ms0), fb0 = __expf(mb0 - ms0);
            float f01 = __expf(m1 - ms1), fa1 = __expf(ma1 - ms1), fb1 = __expf(mb1 - ms1);
            float inv0 = 1.f / (l0 * f00 + la0 * fa0 + lb0 * fb0);
            float inv1 = 1.f / (l1 * f01 + la1 * fa1 + lb1 * fb1);
            float* ob = out + ((size_t)b * Tn + qt * 64 + wq * 16 + gr) * Hn;
#pragma unroll
            for (int nt = 0; nt < 8; nt++) {
                float2 a0 = *(const float2*)&M1[r0 * AS + nt * 8 + 2 * t];
                float2 a1 = *(const float2*)&M1[r1 * AS + nt * 8 + 2 * t];
                float2 b0 = *(const float2*)&M2[r0 * AS + nt * 8 + 2 * t];
                float2 b1 = *(const float2*)&M2[r1 * AS + nt * 8 + 2 * t];
                *(float2*)&ob[nt * 8 + 2 * t] = make_float2(
                    (o[nt][0] * f00 + a0.x * fa0 + b0.x * fb0) * inv0,
                    (o[nt][1] * f00 + a0.y * fa0 + b0.y * fb0) * inv0);
                *(float2*)&ob[(size_t)8 * Hn + nt * 8 + 2 * t] = make_float2(
                    (o[nt][2] * f01 + a1.x * fa1 + b1.x * fb1) * inv1,
                    (o[nt][3] * f01 + a1.y * fa1 + b1.y * fb1) * inv1);
            }
        }
    }
}

// ================= launcher =================
extern "C" void kernel_launch(void* const* d_in, const int* in_sizes, int n_in,
                              void* d_out, int out_size)
{
    const float* x  = (const float*)d_in[0];
    const float* Wq = (const float*)d_in[1];
    const float* Wk = (const float*)d_in[2];
    const float* Wv = (const float*)d_in[3];
    float* out = (float*)d_out;

    int qkv_smem = 2 * (64 * XS_ST + PKC * WS_ST) * (int)sizeof(float);   // 68608
    cudaFuncSetAttribute(qkv_kernel, cudaFuncAttributeMaxDynamicSharedMemorySize, qkv_smem);
    qkv_kernel<<<(Bn * Tn) / 64, 128, qkv_smem>>>(x, Wq, Wk, Wv);

    int attn_smem = 10 * 64 * AS * (int)sizeof(uu);                       // 174080
    cudaFuncSetAttribute(attn_kernel, cudaFuncAttributeMaxDynamicSharedMemorySize, attn_smem);
    attn_kernel<<<Bn * 32, 384, attn_smem>>>(out);
}

// round 5
// speedup vs baseline: 3.7493x; 1.1108x over previous
#include <cuda_runtime.h>

#define Bn 4
#define Tn 4096
#define En 1024
#define Hn 64
#define SCALE 0.03125f   // 1024^-0.5

typedef unsigned uu;

// Projected q/k/v scratch: [B,T,H] fp32
__device__ float g_q[Bn * Tn * Hn];
__device__ float g_k[Bn * Tn * Hn];
__device__ float g_v[Bn * Tn * Hn];

__device__ __forceinline__ uu f2tf(float f) {
    uu r; asm("cvt.rna.tf32.f32 %0, %1;" : "=r"(r) : "f"(f)); return r;
}

// D += A(16x8,row) * B(8x8,col), tf32 in, fp32 accum
__device__ __forceinline__ void mma8(float c[4], const uu a[4], const uu b[2]) {
    asm("mma.sync.aligned.m16n8k8.row.col.f32.tf32.tf32.f32 "
        "{%0,%1,%2,%3}, {%4,%5,%6,%7}, {%8,%9}, {%0,%1,%2,%3};"
        : "+f"(c[0]), "+f"(c[1]), "+f"(c[2]), "+f"(c[3])
        : "r"(a[0]), "r"(a[1]), "r"(a[2]), "r"(a[3]), "r"(b[0]), "r"(b[1]));
}

// group-scoped named barrier (128 threads)
__device__ __forceinline__ void barg(int id) {
    asm volatile("bar.sync %0, %1;" :: "r"(id), "r"(128) : "memory");
}

__device__ __forceinline__ void cpa16(void* s, const void* g) {
    unsigned sa = (unsigned)__cvta_generic_to_shared(s);
    asm volatile("cp.async.ca.shared.global [%0], [%1], 16;" :: "r"(sa), "l"(g));
}
__device__ __forceinline__ void cpa_commit() {
    asm volatile("cp.async.commit_group;" ::: "memory");
}
__device__ __forceinline__ void cpa_wait1() {
    asm volatile("cp.async.wait_group 1;" ::: "memory");
}

// ================= QKV projection (unchanged from R4) =================
#define PKC 32
#define XS_ST 36
#define WS_ST 196

__global__ void __launch_bounds__(128, 2) qkv_kernel(
    const float* __restrict__ x,  const float* __restrict__ Wq,
    const float* __restrict__ Wk, const float* __restrict__ Wv)
{
    extern __shared__ float smf[];
    float* xsb = smf;
    float* wsb = smf + 2 * 64 * XS_ST;

    const int tid = threadIdx.x;
    const int w = tid >> 5, lane = tid & 31, gr = lane >> 2, t = lane & 3;
    const int row0 = blockIdx.x * 64;
    const float* Ws[3] = { Wq, Wk, Wv };

    float acc[4][6][4];
#pragma unroll
    for (int rb = 0; rb < 4; rb++)
#pragma unroll
        for (int nt = 0; nt < 6; nt++)
#pragma unroll
            for (int c = 0; c < 4; c++) acc[rb][nt][c] = 0.f;

    auto issue = [&](int k0, int s) {
        float* xs = xsb + s * 64 * XS_ST;
        float* ws = wsb + s * PKC * WS_ST;
#pragma unroll
        for (int it = 0; it < 4; it++) {
            int idx = tid + it * 128;
            int r = idx >> 3, c = (idx & 7) * 4;
            cpa16(&xs[r * XS_ST + c], &x[(size_t)(row0 + r) * En + k0 + c]);
        }
#pragma unroll
        for (int it = 0; it < 12; it++) {
            int idx = tid + it * 128;
            int kk = idx / 48, n4 = (idx % 48) * 4;
            int m = n4 >> 6, col = n4 & 63;
            cpa16(&ws[kk * WS_ST + n4], &Ws[m][(size_t)(k0 + kk) * Hn + col]);
        }
    };

    issue(0, 0);
    cpa_commit();

    for (int it = 0; it < En / PKC; it++) {
        __syncthreads();
        if (it + 1 < En / PKC) issue((it + 1) * PKC, (it + 1) & 1);
        cpa_commit();
        cpa_wait1();
        __syncthreads();

        const float* xs = xsb + (it & 1) * 64 * XS_ST;
        const float* ws = wsb + (it & 1) * PKC * WS_ST;
#pragma unroll
        for (int kk = 0; kk < PKC / 8; kk++) {
            uu a[4][4];
#pragma unroll
            for (int rb = 0; rb < 4; rb++) {
                int r = rb * 16 + gr;
                a[rb][0] = f2tf(xs[r * XS_ST + kk * 8 + t]);
                a[rb][1] = f2tf(xs[(r + 8) * XS_ST + kk * 8 + t]);
                a[rb][2] = f2tf(xs[r * XS_ST + kk * 8 + t + 4]);
                a[rb][3] = f2tf(xs[(r + 8) * XS_ST + kk * 8 + t + 4]);
            }
#pragma unroll
            for (int nt = 0; nt < 6; nt++) {
                int n0 = w * 48 + nt * 8;
                uu b[2];
                b[0] = f2tf(ws[(kk * 8 + t) * WS_ST + n0 + gr]);
                b[1] = f2tf(ws[(kk * 8 + t + 4) * WS_ST + n0 + gr]);
#pragma unroll
                for (int rb = 0; rb < 4; rb++) mma8(acc[rb][nt], a[rb], b);
            }
        }
    }

#pragma unroll
    for (int nt = 0; nt < 6; nt++) {
        int n = w * 48 + nt * 8 + 2 * t;
        float* base = (n < 64) ? g_q : (n < 128 ? g_k : g_v);
        int nc = n & 63;
#pragma unroll
        for (int rb = 0; rb < 4; rb++) {
            int r = row0 + rb * 16 + gr;
            *(float2*)&base[(size_t)r * Hn + nc] =
                make_float2(acc[rb][nt][0], acc[rb][nt][1]);
            *(float2*)&base[(size_t)(r + 8) * Hn + nc] =
                make_float2(acc[rb][nt][2], acc[rb][nt][3]);
        }
    }
}

// ================= Flash attention: 3 kt-groups x (2x2) 32x32 warp tiles =================
// Block 384 thr = 3 groups x 4 warps. Group g: kt % 3 == g, private K/V strips.
// Warp (rw,cw) in group: S rows rw*32..+31, cols cw*32..+31. Independent online
// softmax per warp (col-split = split-K); 6 partials merged per q-tile at the end.
// P stays in registers; stage-2 A-frags built via shuffles.
#define AS 68
#define NG 3

__global__ void __launch_bounds__(384, 1) attn_kernel(float* __restrict__ out)
{
    extern __shared__ uu sm[];
    const int tid = threadIdx.x;
    const int w = tid >> 5, lane = tid & 31, gr = lane >> 2, t = lane & 3;
    const int g = w >> 2, wq = w & 3;
    const int rw = wq >> 1, cw = wq & 1;
    const int tg = tid & 127;

    uu* qs  = sm;                                  // Q tile (tf32, scale folded)
    uu* ksg = sm + (size_t)(1 + g) * 64 * AS;      // strips 1..3
    uu* vsg = sm + (size_t)(4 + g) * 64 * AS;      // strips 4..6
    float* Mg = (float*)(sm + (size_t)(1 + 2 * g + cw) * 64 * AS);  // merge (aliases K/V)

    const int b = blockIdx.x & 3, pr = blockIdx.x >> 2;
    const float* kg = g_k + (size_t)b * Tn * Hn;
    const float* vg = g_v + (size_t)b * Tn * Hn;

    const int rbase = rw * 32, cbase = cw * 32;
    const int srcA = (lane & ~3) | (t >> 1);   // shuffle source lanes for P->A frag
    const int srcB = srcA + 2;

    for (int hf = 0; hf < 2; hf++) {
        const int qt = hf ? pr : 63 - pr;
        __syncthreads();   // previous half's merge readers done

        // Q tile -> smem (tf32, SCALE folded), all 384 threads
        const float* qg = g_q + ((size_t)b * Tn + qt * 64) * Hn;
        for (int idx = tid; idx < 1024; idx += 384) {
            int r = idx >> 4, c = (idx & 15) * 4;
            float4 v = *(const float4*)&qg[(size_t)r * Hn + c];
            *(uint4*)&qs[r * AS + c] = make_uint4(
                f2tf(v.x * SCALE), f2tf(v.y * SCALE),
                f2tf(v.z * SCALE), f2tf(v.w * SCALE));
        }
        __syncthreads();

        float o[2][8][4];                 // [rb][ht][c] : 32 rows x 64 h partial
        float mm[2][2], ll[2][2];         // [rb][row: gr / gr+8]
#pragma unroll
        for (int rb = 0; rb < 2; rb++) {
            mm[rb][0] = mm[rb][1] = -1e30f;
            ll[rb][0] = ll[rb][1] = 0.f;
#pragma unroll
            for (int ht = 0; ht < 8; ht++)
#pragma unroll
                for (int c = 0; c < 4; c++) o[rb][ht][c] = 0.f;
        }

        for (int kt = g; kt <= qt; kt += NG) {
            barg(g + 1);   // group's readers done with ksg/vsg
            const float* kp = kg + (size_t)kt * 64 * Hn;
            const float* vp = vg + (size_t)kt * 64 * Hn;
#pragma unroll
            for (int it = 0; it < 8; it++) {
                int idx = tg + it * 128;
                int r = idx >> 4, c = (idx & 15) * 4;
                float4 kv = *(const float4*)&kp[(size_t)r * Hn + c];
                *(uint4*)&ksg[r * AS + c] =
                    make_uint4(f2tf(kv.x), f2tf(kv.y), f2tf(kv.z), f2tf(kv.w));
                float4 vv = *(const float4*)&vp[(size_t)r * Hn + c];
                *(uint4*)&vsg[r * AS + c] =
                    make_uint4(f2tf(vv.x), f2tf(vv.y), f2tf(vv.z), f2tf(vv.w));
            }
            barg(g + 1);

            // ---- stage 1: S(32x32) = Q K^T ----
            float s[2][4][4];
#pragma unroll
            for (int rb = 0; rb < 2; rb++)
#pragma unroll
                for (int nt = 0; nt < 4; nt++)
#pragma unroll
                    for (int c = 0; c < 4; c++) s[rb][nt][c] = 0.f;
#pragma unroll
            for (int kk = 0; kk < 8; kk++) {
                uu qa[2][4];
#pragma unroll
                for (int rb = 0; rb < 2; rb++) {
                    int ra = (rbase + rb * 16 + gr) * AS;
                    qa[rb][0] = qs[ra + kk * 8 + t];
                    qa[rb][1] = qs[ra + 8 * AS + kk * 8 + t];
                    qa[rb][2] = qs[ra + kk * 8 + t + 4];
                    qa[rb][3] = qs[ra + 8 * AS + kk * 8 + t + 4];
                }
#pragma unroll
                for (int nt = 0; nt < 4; nt++) {
                    uu bf[2];
                    int kr = (cbase + nt * 8 + gr) * AS;
                    bf[0] = ksg[kr + kk * 8 + t];
                    bf[1] = ksg[kr + kk * 8 + t + 4];
                    mma8(s[0][nt], qa[0], bf);
                    mma8(s[1][nt], qa[1], bf);
                }
            }

            if (kt == qt) {   // causal mask on diagonal tile (local 64x64 coords)
#pragma unroll
                for (int rb = 0; rb < 2; rb++) {
                    int r0 = rbase + rb * 16 + gr, r1 = r0 + 8;
#pragma unroll
                    for (int nt = 0; nt < 4; nt++) {
                        int c0 = cbase + nt * 8 + 2 * t;
                        if (c0 > r0)     s[rb][nt][0] = -1e30f;
                        if (c0 + 1 > r0) s[rb][nt][1] = -1e30f;
                        if (c0 > r1)     s[rb][nt][2] = -1e30f;
                        if (c0 + 1 > r1) s[rb][nt][3] = -1e30f;
                    }
                }
            }

            // ---- online softmax (per rb; this warp's 32-col strip) ----
#pragma unroll
            for (int rb = 0; rb < 2; rb++) {
                float rm0 = -1e30f, rm1 = -1e30f;
#pragma unroll
                for (int nt = 0; nt < 4; nt++) {
                    rm0 = fmaxf(rm0, fmaxf(s[rb][nt][0], s[rb][nt][1]));
                    rm1 = fmaxf(rm1, fmaxf(s[rb][nt][2], s[rb][nt][3]));
                }
                rm0 = fmaxf(rm0, __shfl_xor_sync(~0u, rm0, 1));
                rm0 = fmaxf(rm0, __shfl_xor_sync(~0u, rm0, 2));
                rm1 = fmaxf(rm1, __shfl_xor_sync(~0u, rm1, 1));
                rm1 = fmaxf(rm1, __shfl_xor_sync(~0u, rm1, 2));
                float nm0 = fmaxf(mm[rb][0], rm0), nm1 = fmaxf(mm[rb][1], rm1);
                float cr0 = __expf(mm[rb][0] - nm0), cr1 = __expf(mm[rb][1] - nm1);
                mm[rb][0] = nm0; mm[rb][1] = nm1;

                float rs0 = 0.f, rs1 = 0.f;
#pragma unroll
                for (int nt = 0; nt < 4; nt++) {
                    float p0 = __expf(s[rb][nt][0] - nm0), p1 = __expf(s[rb][nt][1] - nm0);
                    float p2 = __expf(s[rb][nt][2] - nm1), p3 = __expf(s[rb][nt][3] - nm1);
                    rs0 += p0 + p1; rs1 += p2 + p3;
                    // store tf32 bits in place (P stays in these registers)
                    s[rb][nt][0] = __uint_as_float(f2tf(p0));
                    s[rb][nt][1] = __uint_as_float(f2tf(p1));
                    s[rb][nt][2] = __uint_as_float(f2tf(p2));
                    s[rb][nt][3] = __uint_as_float(f2tf(p3));
                }
                rs0 += __shfl_xor_sync(~0u, rs0, 1);
                rs0 += __shfl_xor_sync(~0u, rs0, 2);
                rs1 += __shfl_xor_sync(~0u, rs1, 1);
                rs1 += __shfl_xor_sync(~0u, rs1, 2);
                ll[rb][0] = ll[rb][0] * cr0 + rs0;
                ll[rb][1] = ll[rb][1] * cr1 + rs1;
#pragma unroll
                for (int ht = 0; ht < 8; ht++) {
                    o[rb][ht][0] *= cr0; o[rb][ht][1] *= cr0;
                    o[rb][ht][2] *= cr1; o[rb][ht][3] *= cr1;
                }
            }

            // ---- stage 2: O += P V (P A-frags via shuffle, V rows cbase..+31) ----
#pragma unroll
            for (int kk = 0; kk < 4; kk++) {
                uu pa[2][4];
#pragma unroll
                for (int rb = 0; rb < 2; rb++) {
                    float u0 = __shfl_sync(~0u, s[rb][kk][0], srcA);
                    float u1 = __shfl_sync(~0u, s[rb][kk][1], srcA);
                    float u2 = __shfl_sync(~0u, s[rb][kk][2], srcA);
                    float u3 = __shfl_sync(~0u, s[rb][kk][3], srcA);
                    float v0 = __shfl_sync(~0u, s[rb][kk][0], srcB);
                    float v1 = __shfl_sync(~0u, s[rb][kk][1], srcB);
                    float v2 = __shfl_sync(~0u, s[rb][kk][2], srcB);
                    float v3 = __shfl_sync(~0u, s[rb][kk][3], srcB);
                    pa[rb][0] = __float_as_uint((t & 1) ? u1 : u0);
                    pa[rb][1] = __float_as_uint((t & 1) ? u3 : u2);
                    pa[rb][2] = __float_as_uint((t & 1) ? v1 : v0);
                    pa[rb][3] = __float_as_uint((t & 1) ? v3 : v2);
                }
#pragma unroll
                for (int ht = 0; ht < 8; ht++) {
                    uu vb[2];
                    vb[0] = vsg[(cbase + kk * 8 + t) * AS + ht * 8 + gr];
                    vb[1] = vsg[(cbase + kk * 8 + t + 4) * AS + ht * 8 + gr];
                    mma8(o[0][ht], pa[0], vb);
                    mma8(o[1][ht], pa[1], vb);
                }
            }
        }

        // ---- dump 6 partials into strips 1..6 (K/V strips are dead now) ----
        __syncthreads();
#pragma unroll
        for (int rb = 0; rb < 2; rb++) {
            int r0 = rbase + rb * 16 + gr, r1 = r0 + 8;
#pragma unroll
            for (int ht = 0; ht < 8; ht++) {
                *(float2*)&Mg[r0 * AS + ht * 8 + 2 * t] = make_float2(o[rb][ht][0], o[rb][ht][1]);
                *(float2*)&Mg[r1 * AS + ht * 8 + 2 * t] = make_float2(o[rb][ht][2], o[rb][ht][3]);
            }
            if (t == 0) {
                Mg[r0 * AS + 64] = mm[rb][0]; Mg[r0 * AS + 65] = ll[rb][0];
                Mg[r1 * AS + 64] = mm[rb][1]; Mg[r1 * AS + 65] = ll[rb][1];
            }
        }
        __syncthreads();

        // ---- combine 6 partials, write output ----
        float* ob = out + ((size_t)b * Tn + qt * 64) * Hn;
        for (int idx = tid; idx < 1024; idx += 384) {
            int r = idx >> 4, c4 = (idx & 15) * 4;
            float mi[6], li[6], Mx = -1e30f;
#pragma unroll
            for (int i = 0; i < 6; i++) {
                const float* Mi = (const float*)(sm + (size_t)(1 + i) * 64 * AS);
                mi[i] = Mi[r * AS + 64];
                li[i] = Mi[r * AS + 65];
                Mx = fmaxf(Mx, mi[i]);
            }
            float L = 0.f, fi[6];
#pragma unroll
            for (int i = 0; i < 6; i++) {
                fi[i] = __expf(mi[i] - Mx);
                L += li[i] * fi[i];
            }
            float4 acc = make_float4(0.f, 0.f, 0.f, 0.f);
#pragma unroll
            for (int i = 0; i < 6; i++) {
                const float* Mi = (const float*)(sm + (size_t)(1 + i) * 64 * AS);
                float4 v = *(const float4*)&Mi[r * AS + c4];
                acc.x += fi[i] * v.x; acc.y += fi[i] * v.y;
                acc.z += fi[i] * v.z; acc.w += fi[i] * v.w;
            }
            float inv = 1.f / L;
            acc.x *= inv; acc.y *= inv; acc.z *= inv; acc.w *= inv;
            *(float4*)&ob[(size_t)r * Hn + c4] = acc;
        }
    }
}

// ================= launcher =================
extern "C" void kernel_launch(void* const* d_in, const int* in_sizes, int n_in,
                              void* d_out, int out_size)
{
    const float* x  = (const float*)d_in[0];
    const float* Wq = (const float*)d_in[1];
    const float* Wk = (const float*)d_in[2];
    const float* Wv = (const float*)d_in[3];
    float* out = (float*)d_out;

    int qkv_smem = 2 * (64 * XS_ST + PKC * WS_ST) * (int)sizeof(float);   // 68608
    cudaFuncSetAttribute(qkv_kernel, cudaFuncAttributeMaxDynamicSharedMemorySize, qkv_smem);
    qkv_kernel<<<(Bn * Tn) / 64, 128, qkv_smem>>>(x, Wq, Wk, Wv);

    int attn_smem = 7 * 64 * AS * (int)sizeof(uu);                        // 121856
    cudaFuncSetAttribute(attn_kernel, cudaFuncAttributeMaxDynamicSharedMemorySize, attn_smem);
    attn_kernel<<<Bn * 32, 384, attn_smem>>>(out);
}